// round 4
// baseline (speedup 1.0000x reference)
#include <cuda_runtime.h>
#include <math.h>

// Problem constants (fixed by the reference)
#define Bn    8
#define Tn    128
#define Un    64
#define U1    65        // U + 1
#define Vn    1024
#define BLANKC 1023     // blank = V-1
#define NEGF  (-1e30f)
#define SPAD  66        // padded row stride for shared tiles (conflict-free)

// Scratch: per-row log-probs needed by the DP.
__device__ float g_lp_blank[Bn * Tn * U1];
__device__ float g_lp_emit[Bn * Tn * Un];

// ---------------------------------------------------------------------------
// Kernel A: one warp per (b,t,u) row of V=1024 logits.  (at HBM roofline)
// ---------------------------------------------------------------------------
__global__ void __launch_bounds__(256)
lse_gather_kernel(const float* __restrict__ logits,
                  const int* __restrict__ targets)
{
    const int warp_id = (blockIdx.x * blockDim.x + threadIdx.x) >> 5;
    const int lane    = threadIdx.x & 31;
    const int nrows   = Bn * Tn * U1;
    if (warp_id >= nrows) return;

    const float4* row4 = reinterpret_cast<const float4*>(
        logits + (size_t)warp_id * Vn);

    float4 v[8];
#pragma unroll
    for (int i = 0; i < 8; i++) v[i] = row4[lane + 32 * i];

    float m = -INFINITY;
#pragma unroll
    for (int i = 0; i < 8; i++) {
        m = fmaxf(m, fmaxf(fmaxf(v[i].x, v[i].y), fmaxf(v[i].z, v[i].w)));
    }
#pragma unroll
    for (int o = 16; o > 0; o >>= 1)
        m = fmaxf(m, __shfl_xor_sync(0xffffffffu, m, o));

    float s = 0.f;
#pragma unroll
    for (int i = 0; i < 8; i++) {
        s += __expf(v[i].x - m) + __expf(v[i].y - m)
           + __expf(v[i].z - m) + __expf(v[i].w - m);
    }
#pragma unroll
    for (int o = 16; o > 0; o >>= 1)
        s += __shfl_xor_sync(0xffffffffu, s, o);

    if (lane == 0) {
        const float lse = m + logf(s);
        const int b   = warp_id / (Tn * U1);
        const int rem = warp_id % (Tn * U1);
        const int t   = rem / U1;
        const int u   = rem % U1;
        const float* rowf = logits + (size_t)warp_id * Vn;
        g_lp_blank[warp_id] = rowf[BLANKC] - lse;
        if (u < Un) {
            const int tgt = targets[b * Un + u];
            g_lp_emit[(b * Tn + t) * Un + u] = rowf[tgt] - lse;
        }
    }
}

// ---------------------------------------------------------------------------
// Fast logaddexp: both args finite (NEGF sentinel, never -inf), so
// mn-mx <= 0, __expf in [0,1], __logf(1+s) safe. Two MUFU ops on the chain.
// ---------------------------------------------------------------------------
__device__ __forceinline__ float laexp(float x, float y)
{
    const float mx = fmaxf(x, y);
    const float mn = fminf(x, y);
    return mx + __logf(1.0f + __expf(mn - mx));
}

// ---------------------------------------------------------------------------
// Kernel B: barrier-free single-warp anti-diagonal wavefront.
// One block (128 threads) per batch: all 128 threads preload the lp tiles
// into shared, then warp 0 runs the DP with register-resident alpha:
//   lane l owns u = l (a0) and u = l+32 (a1); u = 64 (a2) is computed
//   redundantly on all lanes from broadcast inputs.
// Diagonal exchange is pure shfl — no __syncthreads in the loop.
// ---------------------------------------------------------------------------
__global__ void __launch_bounds__(128)
rnnt_dp_kernel(const int* __restrict__ logit_lengths,
               const int* __restrict__ target_lengths,
               float* __restrict__ out)
{
    const int b   = blockIdx.x;
    const int tid = threadIdx.x;

    __shared__ float s_lpb[Tn * SPAD];
    __shared__ float s_lpe[Tn * SPAD];

    // ---- preload (coalesced reads, all data L2-resident from kernel A) ----
    {
        const float* lpb_g = g_lp_blank + b * Tn * U1;
        const float* lpe_g = g_lp_emit  + b * Tn * Un;
        for (int i = tid; i < Tn * U1; i += 128) {
            const int t = i / U1, c = i - t * U1;
            s_lpb[t * SPAD + c] = lpb_g[i];
        }
        for (int i = tid; i < Tn * Un; i += 128) {
            const int t = i / Un, c = i - t * Un;
            s_lpe[t * SPAD + c] = lpe_g[i];
        }
    }
    __syncthreads();
    if (tid >= 32) return;

    const int lane   = tid;
    const int t_last = logit_lengths[b] - 1;
    const int u_last = target_lengths[b];
    const unsigned FULL = 0xffffffffu;

    // alpha registers (previous diagonal). Stale/out-of-range cells keep
    // NEGF or their last value; they are never consumed (see invariant:
    // consumer (t',u+1) at diag d+1 has t' = t, same validity).
    float a0 = (lane == 0) ? 0.f : NEGF;   // u = lane   (alpha[0][0] = 0)
    float a1 = NEGF;                        // u = lane + 32
    float a2 = NEGF;                        // u = 64

    for (int d = 1; d < Tn + Un; d++) {
        // Exchange: values from the previous diagonal.
        const float p0  = __shfl_up_sync(FULL, a0, 1);   // prev[u-1], u=lane
        const float b31 = __shfl_sync(FULL, a0, 31);     // prev[31]
        float       p1  = __shfl_up_sync(FULL, a1, 1);   // prev[u-1], u=lane+32
        if (lane == 0) p1 = b31;
        const float p2  = __shfl_sync(FULL, a1, 31);     // prev[63]

        // ---- u = lane ----
        {
            const int u = lane, t = d - u;
            if (t >= 0 && t < Tn) {
                const float up   = (t > 0) ? a0 + s_lpb[(t - 1) * SPAD + u] : NEGF;
                const float left = (u > 0) ? p0 + s_lpe[t * SPAD + (u - 1)] : NEGF;
                const float v = laexp(up, left);
                a0 = v;
                if (t == t_last && u == u_last)
                    out[b] = -(v + s_lpb[t * SPAD + u]);
            }
        }
        // ---- u = lane + 32 ----
        {
            const int u = lane + 32, t = d - u;
            if (t >= 0 && t < Tn) {
                const float up   = (t > 0) ? a1 + s_lpb[(t - 1) * SPAD + u] : NEGF;
                const float left = p1 + s_lpe[t * SPAD + (u - 1)];
                const float v = laexp(up, left);
                a1 = v;
                if (t == t_last && u == u_last)
                    out[b] = -(v + s_lpb[t * SPAD + u]);
            }
        }
        // ---- u = 64 (redundant on all lanes; broadcast smem reads) ----
        {
            const int t = d - 64;
            if (t >= 0 && t < Tn) {
                const float up   = (t > 0) ? a2 + s_lpb[(t - 1) * SPAD + 64] : NEGF;
                const float left = p2 + s_lpe[t * SPAD + 63];
                const float v = laexp(up, left);
                a2 = v;
                if (lane == 0 && t == t_last && 64 == u_last)
                    out[b] = -(v + s_lpb[t * SPAD + 64]);
            }
        }
    }
}

// ---------------------------------------------------------------------------
// Launch
// ---------------------------------------------------------------------------
extern "C" void kernel_launch(void* const* d_in, const int* in_sizes, int n_in,
                              void* d_out, int out_size)
{
    const float* logits         = (const float*)d_in[0];
    const int*   targets        = (const int*)d_in[1];
    const int*   logit_lengths  = (const int*)d_in[2];
    const int*   target_lengths = (const int*)d_in[3];
    float*       out            = (float*)d_out;

    const int nrows   = Bn * Tn * U1;          // 66560 rows, one warp each
    const int threads = 256;
    const int blocks  = (nrows * 32 + threads - 1) / threads;

    lse_gather_kernel<<<blocks, threads>>>(logits, targets);
    rnnt_dp_kernel<<<Bn, 128>>>(logit_lengths, target_lengths, out);
}

// round 6
// speedup vs baseline: 1.4009x; 1.4009x over previous
#include <cuda_runtime.h>
#include <math.h>

// Problem constants (fixed by the reference)
#define Bn    8
#define Tn    128
#define Un    64
#define U1    65        // U + 1
#define Vn    1024
#define BLANKC 1023     // blank = V-1
#define NEGF  (-1e30f)
#define SPAD  66        // padded row stride for shared tiles (conflict-free)

// Scratch: per-row log-probs needed by the DP.
__device__ float g_lp_blank[Bn * Tn * U1];
__device__ float g_lp_emit[Bn * Tn * Un];

// ---------------------------------------------------------------------------
// Kernel A: one warp per (b,t,u) row of V=1024 logits.  (at HBM roofline)
// ---------------------------------------------------------------------------
__global__ void __launch_bounds__(256)
lse_gather_kernel(const float* __restrict__ logits,
                  const int* __restrict__ targets)
{
    const int warp_id = (blockIdx.x * blockDim.x + threadIdx.x) >> 5;
    const int lane    = threadIdx.x & 31;
    const int nrows   = Bn * Tn * U1;
    if (warp_id >= nrows) return;

    const float4* row4 = reinterpret_cast<const float4*>(
        logits + (size_t)warp_id * Vn);

    float4 v[8];
#pragma unroll
    for (int i = 0; i < 8; i++) v[i] = row4[lane + 32 * i];

    float m = -INFINITY;
#pragma unroll
    for (int i = 0; i < 8; i++) {
        m = fmaxf(m, fmaxf(fmaxf(v[i].x, v[i].y), fmaxf(v[i].z, v[i].w)));
    }
#pragma unroll
    for (int o = 16; o > 0; o >>= 1)
        m = fmaxf(m, __shfl_xor_sync(0xffffffffu, m, o));

    float s = 0.f;
#pragma unroll
    for (int i = 0; i < 8; i++) {
        s += __expf(v[i].x - m) + __expf(v[i].y - m)
           + __expf(v[i].z - m) + __expf(v[i].w - m);
    }
#pragma unroll
    for (int o = 16; o > 0; o >>= 1)
        s += __shfl_xor_sync(0xffffffffu, s, o);

    if (lane == 0) {
        const float lse = m + logf(s);
        const int b   = warp_id / (Tn * U1);
        const int rem = warp_id % (Tn * U1);
        const int t   = rem / U1;
        const int u   = rem % U1;
        const float* rowf = logits + (size_t)warp_id * Vn;
        g_lp_blank[warp_id] = rowf[BLANKC] - lse;
        if (u < Un) {
            const int tgt = targets[b * Un + u];
            g_lp_emit[(b * Tn + t) * Un + u] = rowf[tgt] - lse;
        }
    }
}

// ---------------------------------------------------------------------------
// Fast logaddexp: args are finite (NEGF sentinel, never -inf), mn-mx <= 0,
// __expf in [0,1], __logf(1+s) safe. Two MUFU ops on the chain.
// ---------------------------------------------------------------------------
__device__ __forceinline__ float laexp(float x, float y)
{
    const float mx = fmaxf(x, y);
    const float mn = fminf(x, y);
    return mx + __logf(1.0f + __expf(mn - mx));
}

__device__ __forceinline__ int clampt(int t)
{
    return min(max(t, 0), Tn - 1);
}

// ---------------------------------------------------------------------------
// Kernel B: branchless single-warp anti-diagonal wavefront.
// Lane l owns u=l (a0) and u=l+32 (a1); u=64 (a2) is replicated on all lanes.
// All updates are UNCONDITIONAL: out-of-range cells (t<0 or t>=Tn) compute
// harmless garbage (stays ~ -1e30, log-probs are <0 so no upward drift, no
// overflow/NaN) and are never consumed by valid cells — the consumer of
// (t,u) at diag d+1 sits at the same t, so validity is inherited.
// Loop runs exactly to d_star = t_last + u_last; loss extracted afterwards.
// ---------------------------------------------------------------------------
__global__ void __launch_bounds__(128)
rnnt_dp_kernel(const int* __restrict__ logit_lengths,
               const int* __restrict__ target_lengths,
               float* __restrict__ out)
{
    const int b   = blockIdx.x;
    const int tid = threadIdx.x;

    __shared__ float s_lpb[Tn * SPAD];
    __shared__ float s_lpe[Tn * SPAD];

    // ---- preload (coalesced reads, data is L2-resident from kernel A) ----
    {
        const float* lpb_g = g_lp_blank + b * Tn * U1;
        const float* lpe_g = g_lp_emit  + b * Tn * Un;
        for (int i = tid; i < Tn * U1; i += 128) {
            const int t = i / U1, c = i - t * U1;
            s_lpb[t * SPAD + c] = lpb_g[i];
        }
        for (int i = tid; i < Tn * Un; i += 128) {
            const int t = i / Un, c = i - t * Un;
            s_lpe[t * SPAD + c] = lpe_g[i];
        }
    }
    __syncthreads();
    if (tid >= 32) return;

    const int lane   = tid;
    const int t_last = logit_lengths[b] - 1;
    const int u_last = target_lengths[b];
    const int d_star = t_last + u_last;          // in [95, 191]
    const unsigned FULL = 0xffffffffu;

    const int um1_0 = max(lane - 1, 0);          // clamped u-1 for segment 0

    float a0 = (lane == 0) ? 0.f : NEGF;         // u = lane   (alpha[0][0]=0)
    float a1 = NEGF;                             // u = lane + 32
    float a2 = NEGF;                             // u = 64

    for (int d = 1; d <= d_star; d++) {
        // exchange previous-diagonal values (no predication beyond SELs)
        float p0        = __shfl_up_sync(FULL, a0, 1);
        const float b31 = __shfl_sync(FULL, a0, 31);
        float p1        = __shfl_up_sync(FULL, a1, 1);
        const float p2  = __shfl_sync(FULL, a1, 31);
        if (lane == 0) { p0 = NEGF; p1 = b31; }  // -> 2 SELs

        // ---- segment 0: u = lane, t = d - lane ----
        {
            const int t  = d - lane;
            const int rb = clampt(t - 1);
            const int re = clampt(t);
            const float up = a0 + s_lpb[rb * SPAD + lane];
            const float lf = p0 + s_lpe[re * SPAD + um1_0];
            a0 = laexp(up, lf);
        }
        // ---- segment 1: u = lane + 32, t = d - lane - 32 ----
        {
            const int t  = d - lane - 32;
            const int rb = clampt(t - 1);
            const int re = clampt(t);
            const float up = a1 + s_lpb[rb * SPAD + lane + 32];
            const float lf = p1 + s_lpe[re * SPAD + lane + 31];
            a1 = laexp(up, lf);
        }
        // ---- segment 2: u = 64 (replicated; broadcast smem reads) ----
        {
            const int t  = d - 64;
            const int rb = clampt(t - 1);
            const int re = clampt(t);
            const float up = a2 + s_lpb[rb * SPAD + 64];
            const float lf = p2 + s_lpe[re * SPAD + 63];
            a2 = laexp(up, lf);
        }
    }

    // ---- extraction: alpha[t_last][u_last] computed on diagonal d_star ----
    float v;
    int owner;
    if (u_last == 64)      { v = a2; owner = 0; }
    else if (u_last >= 32) { v = a1; owner = u_last - 32; }
    else                   { v = a0; owner = u_last; }
    if (lane == owner)
        out[b] = -(v + s_lpb[t_last * SPAD + u_last]);
}

// ---------------------------------------------------------------------------
// Launch
// ---------------------------------------------------------------------------
extern "C" void kernel_launch(void* const* d_in, const int* in_sizes, int n_in,
                              void* d_out, int out_size)
{
    const float* logits         = (const float*)d_in[0];
    const int*   targets        = (const int*)d_in[1];
    const int*   logit_lengths  = (const int*)d_in[2];
    const int*   target_lengths = (const int*)d_in[3];
    float*       out            = (float*)d_out;

    const int nrows   = Bn * Tn * U1;          // 66560 rows, one warp each
    const int threads = 256;
    const int blocks  = (nrows * 32 + threads - 1) / threads;

    lse_gather_kernel<<<blocks, threads>>>(logits, targets);
    rnnt_dp_kernel<<<Bn, 128>>>(logit_lengths, target_lengths, out);
}